// round 1
// baseline (speedup 1.0000x reference)
#include <cuda_runtime.h>
#include <cstdint>
#include <cstring>

// VectorQuantizer: B=131072 rows of D=64 fp32; K=1024 codebook entries.
// out[b] = embeddings[argmin_k ||x_b - e_k||^2]
//
// Score used: s(k) = e_sq[k] - 2 * <x_b, e_k>   (x_sq is a per-row constant,
// so ordering matches the reference's dist2 = x_sq - 2*cross + e_sq).
// Strict '<' with ascending k reproduces jnp.argmin first-occurrence ties.

#define VQ_B 131072
#define VQ_K 1024
#define VQ_D 64
#define ROWS_PER_BLOCK 256
#define CHUNK 128  // codes per smem tile: 128*64*4 = 32 KB

__device__ float g_esq[VQ_K];

// Packed fp32x2 FMA / ADD (Blackwell PTX-only; doubles fp32 FMA throughput).
#define FMA_F32X2(acc, a, b) \
    asm("fma.rn.f32x2 %0, %1, %2, %0;" : "+l"(acc) : "l"(a), "l"(b))
#define ADD_F32X2(d, a, b) \
    asm("add.rn.f32x2 %0, %1, %2;" : "=l"(d) : "l"(a), "l"(b))

static __device__ __forceinline__ uint64_t f2_as_u64(float2 v) {
    uint64_t u;
    memcpy(&u, &v, 8);
    return u;
}
static __device__ __forceinline__ float2 u64_as_f2(uint64_t u) {
    float2 v;
    memcpy(&v, &u, 8);
    return v;
}

__global__ void vq_esq_kernel(const float* __restrict__ e) {
    int k = blockIdx.x * blockDim.x + threadIdx.x;
    if (k < VQ_K) {
        const float4* row = reinterpret_cast<const float4*>(e + (size_t)k * VQ_D);
        float s = 0.f;
#pragma unroll
        for (int i = 0; i < VQ_D / 4; i++) {
            float4 v = row[i];
            s += v.x * v.x + v.y * v.y + v.z * v.z + v.w * v.w;
        }
        g_esq[k] = s;
    }
}

__global__ void __launch_bounds__(ROWS_PER_BLOCK)
vq_argmin_kernel(const float* __restrict__ x,
                 const float* __restrict__ e,
                 float* __restrict__ out) {
    __shared__ float se[CHUNK * VQ_D];  // 32 KB codebook tile
    __shared__ float sesq[CHUNK];

    const int row = blockIdx.x * ROWS_PER_BLOCK + threadIdx.x;

    // x row resident in registers as 32 packed f32x2 (dim pairs).
    uint64_t xr[VQ_D / 2];
    {
        const float2* xrow = reinterpret_cast<const float2*>(x + (size_t)row * VQ_D);
#pragma unroll
        for (int i = 0; i < VQ_D / 2; i++) xr[i] = f2_as_u64(xrow[i]);
    }

    float best = 3.402823466e38f;
    int bestIdx = 0;

    for (int k0 = 0; k0 < VQ_K; k0 += CHUNK) {
        __syncthreads();
        // Cooperative coalesced load of the codebook tile (2048 float4 / 256 thr).
        {
            const float4* src = reinterpret_cast<const float4*>(e + (size_t)k0 * VQ_D);
            float4* dst = reinterpret_cast<float4*>(se);
#pragma unroll
            for (int i = 0; i < (CHUNK * VQ_D / 4) / ROWS_PER_BLOCK; i++)
                dst[threadIdx.x + i * ROWS_PER_BLOCK] = src[threadIdx.x + i * ROWS_PER_BLOCK];
            if (threadIdx.x < CHUNK) sesq[threadIdx.x] = g_esq[k0 + threadIdx.x];
        }
        __syncthreads();

#pragma unroll 4
        for (int c = 0; c < CHUNK; c++) {
            // Code vector: 64 floats = 16 x LDS.128 (broadcast, conflict-free).
            const ulonglong2* ev = reinterpret_cast<const ulonglong2*>(se + c * VQ_D);
            uint64_t acc0 = 0, acc1 = 0, acc2 = 0, acc3 = 0;  // (0.f,0.f) bits
#pragma unroll
            for (int i = 0; i < VQ_D / 8; i++) {  // 8 iters, 2 pairs each
                ulonglong2 ev2a = ev[2 * i];
                ulonglong2 ev2b = ev[2 * i + 1];
                FMA_F32X2(acc0, xr[4 * i + 0], ev2a.x);
                FMA_F32X2(acc1, xr[4 * i + 1], ev2a.y);
                FMA_F32X2(acc2, xr[4 * i + 2], ev2b.x);
                FMA_F32X2(acc3, xr[4 * i + 3], ev2b.y);
            }
            uint64_t s01, s23, s;
            ADD_F32X2(s01, acc0, acc1);
            ADD_F32X2(s23, acc2, acc3);
            ADD_F32X2(s, s01, s23);
            float2 sv = u64_as_f2(s);
            float cross = sv.x + sv.y;
            float score = fmaf(-2.0f, cross, sesq[c]);
            if (score < best) {
                best = score;
                bestIdx = k0 + c;
            }
        }
    }

    // Gather winning embedding (codebook is L2-resident) and write out.
    const float4* src = reinterpret_cast<const float4*>(e + (size_t)bestIdx * VQ_D);
    float4* dst = reinterpret_cast<float4*>(out + (size_t)row * VQ_D);
#pragma unroll
    for (int i = 0; i < VQ_D / 4; i++) dst[i] = src[i];
}

extern "C" void kernel_launch(void* const* d_in, const int* in_sizes, int n_in,
                              void* d_out, int out_size) {
    const float* x = (const float*)d_in[0];          // (131072, 64)
    const float* embeddings = (const float*)d_in[1]; // (1024, 64)
    float* out = (float*)d_out;                      // (131072, 64)

    vq_esq_kernel<<<(VQ_K + 255) / 256, 256>>>(embeddings);
    vq_argmin_kernel<<<VQ_B / ROWS_PER_BLOCK, ROWS_PER_BLOCK>>>(x, embeddings, out);
}

// round 2
// speedup vs baseline: 1.6583x; 1.6583x over previous
#include <cuda_runtime.h>
#include <cstdint>
#include <cstring>
#include <cfloat>

// VectorQuantizer: B=131072 rows, D=64 dims, K=1024 codes, fp32.
// Register-tiled GEMM formulation:
//   block = 128 rows x 64-code chunks (16 chunks), thread = 8 rows x 4 codes.
//   score(k) = e_sq[k] - 2*<x,e_k>  (monotone in true dist2; x_sq constant per row)

#define VQ_B 131072
#define VQ_K 1024
#define VQ_D 64
#define BLK_ROWS 128
#define BLK_THREADS 256
#define CODES_PER_CHUNK 64
#define NCHUNK (VQ_K / CODES_PER_CHUNK)

__device__ float g_esq[VQ_K];
__device__ float g_eT[VQ_D * VQ_K];  // k-major codebook: eT[k][c]

// Packed fp32x2 ops (Blackwell, PTX-only: doubles fp32 FMA throughput).
#define FMA_F32X2(acc, a, b) \
    asm("fma.rn.f32x2 %0, %1, %2, %0;" : "+l"(acc) : "l"(a), "l"(b))
#define DUP_F32X2(d, s) \
    asm("mov.b64 %0, {%1, %1};" : "=l"(d) : "f"(s))

static __device__ __forceinline__ float2 u64_as_f2(uint64_t u) {
    float2 v;
    memcpy(&v, &u, 8);
    return v;
}

// ---------------- prologue 1: e_sq ----------------
__global__ void vq_prep_esq(const float* __restrict__ e) {
    int k = blockIdx.x * blockDim.x + threadIdx.x;
    if (k < VQ_K) {
        const float4* row = reinterpret_cast<const float4*>(e + (size_t)k * VQ_D);
        float s = 0.f;
#pragma unroll
        for (int i = 0; i < VQ_D / 4; i++) {
            float4 v = row[i];
            s += v.x * v.x + v.y * v.y + v.z * v.z + v.w * v.w;
        }
        g_esq[k] = s;
    }
}

// ---------------- prologue 2: transpose codebook to k-major ----------------
__global__ void vq_prep_eT(const float* __restrict__ e) {
    int idx = blockIdx.x * blockDim.x + threadIdx.x;  // 65536
    int c = idx & (VQ_K - 1);
    int k = idx >> 10;
    g_eT[k * VQ_K + c] = e[c * VQ_D + k];  // writes coalesced; reads hit L2
}

// ---------------- main kernel ----------------
__global__ void __launch_bounds__(BLK_THREADS)
vq_main(const float* __restrict__ x,
        const float* __restrict__ e,
        float* __restrict__ out) {
    // xs: k-major x tile, XOR-swizzled granules (8 floats) to dodge transpose
    // store conflicts with zero padding. phys(k,r) = k*128 + ((r>>3 ^ (k>>2)&3)<<3) + (r&7)
    __shared__ float xs[VQ_D * BLK_ROWS];            // 32 KB
    __shared__ float es[VQ_D * CODES_PER_CHUNK];     // 16 KB (k-major, linear)

    const int tid = threadIdx.x;
    const int tx = tid & 15;   // code group: 4 codes
    const int ty = tid >> 4;   // row group:  8 rows (== granule index)
    const int row0 = blockIdx.x * BLK_ROWS;

    // ---- fill xs: transpose 128x64 -> 64x128 (swizzled) ----
#pragma unroll
    for (int i = 0; i < 8; i++) {
        int idx4 = tid + i * BLK_THREADS;       // 2048 float4
        int r = idx4 >> 4, kq = idx4 & 15;
        float4 v = *reinterpret_cast<const float4*>(x + (size_t)(row0 + r) * VQ_D + kq * 4);
        int gfix = (((r >> 3) ^ (kq & 3)) << 3) + (r & 7);  // (k>>2)&3 == kq&3 for all 4 k
        xs[(kq * 4 + 0) * 128 + gfix] = v.x;
        xs[(kq * 4 + 1) * 128 + gfix] = v.y;
        xs[(kq * 4 + 2) * 128 + gfix] = v.z;
        xs[(kq * 4 + 3) * 128 + gfix] = v.w;
    }

    float best[8];
    int bidx[8];
#pragma unroll
    for (int i = 0; i < 8; i++) { best[i] = FLT_MAX; bidx[i] = 0; }

    for (int ch = 0; ch < NCHUNK; ch++) {
        const int cbase = ch * CODES_PER_CHUNK;
        __syncthreads();
        // ---- fill es chunk: straight coalesced copy from k-major eT ----
#pragma unroll
        for (int i = 0; i < 4; i++) {
            int idx4 = tid + i * BLK_THREADS;   // 1024 float4
            int k = idx4 >> 4, cq = idx4 & 15;
            *reinterpret_cast<float4*>(es + k * 64 + cq * 4) =
                *reinterpret_cast<const float4*>(g_eT + k * VQ_K + cbase + cq * 4);
        }
        __syncthreads();

        uint64_t acc[4][4];  // [row-pair][code], f32x2 packed over row pairs
#pragma unroll
        for (int i = 0; i < 4; i++)
#pragma unroll
            for (int c = 0; c < 4; c++) acc[i][c] = 0ull;

#pragma unroll 8
        for (int k = 0; k < VQ_D; k++) {
            int g = ((ty ^ ((k >> 2) & 3)) << 3);
            const ulonglong2* xp = reinterpret_cast<const ulonglong2*>(xs + k * 128 + g);
            ulonglong2 xa = xp[0];  // rows ty*8+0..3 as 2 pairs
            ulonglong2 xb = xp[1];  // rows ty*8+4..7
            float4 ef = *reinterpret_cast<const float4*>(es + k * 64 + tx * 4);
            uint64_t e0, e1, e2, e3;
            DUP_F32X2(e0, ef.x);
            DUP_F32X2(e1, ef.y);
            DUP_F32X2(e2, ef.z);
            DUP_F32X2(e3, ef.w);
            FMA_F32X2(acc[0][0], xa.x, e0); FMA_F32X2(acc[0][1], xa.x, e1);
            FMA_F32X2(acc[0][2], xa.x, e2); FMA_F32X2(acc[0][3], xa.x, e3);
            FMA_F32X2(acc[1][0], xa.y, e0); FMA_F32X2(acc[1][1], xa.y, e1);
            FMA_F32X2(acc[1][2], xa.y, e2); FMA_F32X2(acc[1][3], xa.y, e3);
            FMA_F32X2(acc[2][0], xb.x, e0); FMA_F32X2(acc[2][1], xb.x, e1);
            FMA_F32X2(acc[2][2], xb.x, e2); FMA_F32X2(acc[2][3], xb.x, e3);
            FMA_F32X2(acc[3][0], xb.y, e0); FMA_F32X2(acc[3][1], xb.y, e1);
            FMA_F32X2(acc[3][2], xb.y, e2); FMA_F32X2(acc[3][3], xb.y, e3);
        }

        // ---- per-chunk argmin epilogue (codes ascend -> strict '<' keeps first min) ----
#pragma unroll
        for (int c = 0; c < 4; c++) {
            int code = cbase + tx * 4 + c;
            float eq = __ldg(&g_esq[code]);
#pragma unroll
            for (int i = 0; i < 4; i++) {
                float2 p = u64_as_f2(acc[i][c]);
                float s0 = fmaf(-2.0f, p.x, eq);
                float s1 = fmaf(-2.0f, p.y, eq);
                if (s0 < best[2 * i])     { best[2 * i] = s0;     bidx[2 * i] = code; }
                if (s1 < best[2 * i + 1]) { best[2 * i + 1] = s1; bidx[2 * i + 1] = code; }
            }
        }
    }

    // ---- cross-thread reduction over the 16 code-groups ----
    __syncthreads();
    float* sb = es;                                  // 2048 floats
    int*   si = reinterpret_cast<int*>(es + 2048);   // 2048 ints
#pragma unroll
    for (int i = 0; i < 8; i++) {
        int r = ty * 8 + i;
        sb[r * 16 + tx] = best[i];
        si[r * 16 + tx] = bidx[i];
    }
    int* widx = reinterpret_cast<int*>(xs);
    __syncthreads();
    if (tid < BLK_ROWS) {
        float bs = FLT_MAX;
        int bi = 0;
#pragma unroll
        for (int j = 0; j < 16; j++) {
            float s = sb[tid * 16 + j];
            int id = si[tid * 16 + j];
            if (s < bs || (s == bs && id < bi)) { bs = s; bi = id; }
        }
        widx[tid] = bi;
    }
    __syncthreads();

    // ---- gather winning embeddings, coalesced writes ----
#pragma unroll
    for (int i = 0; i < 8; i++) {
        int idx4 = tid + i * BLK_THREADS;  // 2048 float4
        int r = idx4 >> 4, q = idx4 & 15;
        int id = widx[r];
        *reinterpret_cast<float4*>(out + (size_t)(row0 + r) * VQ_D + q * 4) =
            *reinterpret_cast<const float4*>(e + (size_t)id * VQ_D + q * 4);
    }
}

extern "C" void kernel_launch(void* const* d_in, const int* in_sizes, int n_in,
                              void* d_out, int out_size) {
    const float* x = (const float*)d_in[0];           // (131072, 64)
    const float* embeddings = (const float*)d_in[1];  // (1024, 64)
    float* out = (float*)d_out;                       // (131072, 64)

    vq_prep_esq<<<VQ_K / 256, 256>>>(embeddings);
    vq_prep_eT<<<(VQ_D * VQ_K) / 256, 256>>>(embeddings);
    vq_main<<<VQ_B / BLK_ROWS, BLK_THREADS>>>(x, embeddings, out);
}

// round 4
// speedup vs baseline: 3.0303x; 1.8273x over previous
#include <cuda_runtime.h>
#include <cuda_fp16.h>
#include <cstdint>
#include <cstring>
#include <cfloat>

// VectorQuantizer: B=131072, D=64, K=1024, fp32.
// fp16 mma.sync GEMM + packed-key argmin + margin-certified exact fallback.

#define VQ_B 131072
#define VQ_K 1024
#define VQ_D 64
#define ROWS 128
#define THREADS 256
#define CHUNK 128      // codes per e-chunk
#define NCHUNKS 8

__device__ float g_esq[VQ_K];
__device__ int g_emax2_bits = 0;
__device__ int g_flag_count;
__device__ int g_flag_rows[VQ_B];
__device__ __half g_xh[(size_t)VQ_B * VQ_D];   // fp16 x, granule-swizzled
__device__ __half g_eh[(size_t)VQ_K * VQ_D];   // fp16 e, granule-swizzled

// Dynamic smem layout (bytes)
#define XS_OFF   0        // 128 rows * 128B = 16384
#define ES_OFF   16384    // 2 buffers * 16384
#define ESQ_OFF  49152    // 1024 floats = 4096
#define XSQ_OFF  53248    // 128 floats = 512
#define SMEM_TOTAL 53760

// ---------------- PTX helpers ----------------
static __device__ __forceinline__ uint32_t smem_u32(const void* p) {
    uint32_t a;
    asm("{ .reg .u64 t; cvta.to.shared.u64 t, %1; cvt.u32.u64 %0, t; }" : "=r"(a) : "l"(p));
    return a;
}
#define CP_ASYNC16(dst, src) \
    asm volatile("cp.async.cg.shared.global [%0], [%1], 16;" :: "r"(dst), "l"(src) : "memory")
#define CP_COMMIT() asm volatile("cp.async.commit_group;" ::: "memory")
#define CP_WAIT1() asm volatile("cp.async.wait_group 1;" ::: "memory")
#define CP_WAIT0() asm volatile("cp.async.wait_group 0;" ::: "memory")
#define LDSM_X4(r0, r1, r2, r3, a) \
    asm volatile("ldmatrix.sync.aligned.m8n8.x4.shared.b16 {%0,%1,%2,%3}, [%4];" \
                 : "=r"(r0), "=r"(r1), "=r"(r2), "=r"(r3) : "r"(a))
#define MMA16816(c0, c1, c2, c3, a0, a1, a2, a3, b0, b1) \
    asm volatile("mma.sync.aligned.m16n8k16.row.col.f32.f16.f16.f32 " \
                 "{%0,%1,%2,%3}, {%4,%5,%6,%7}, {%8,%9}, {%0,%1,%2,%3};" \
                 : "+f"(c0), "+f"(c1), "+f"(c2), "+f"(c3) \
                 : "r"(a0), "r"(a1), "r"(a2), "r"(a3), "r"(b0), "r"(b1))

// f32x2 packed math for fallback
#define FMA_F32X2(acc, a, b) asm("fma.rn.f32x2 %0, %1, %2, %0;" : "+l"(acc) : "l"(a), "l"(b))
#define ADD_F32X2(d, a, b) asm("add.rn.f32x2 %0, %1, %2;" : "=l"(d) : "l"(a), "l"(b))
static __device__ __forceinline__ float2 u64f2(uint64_t u) { float2 v; memcpy(&v, &u, 8); return v; }
static __device__ __forceinline__ uint64_t f2u64(float2 v) { uint64_t u; memcpy(&u, &v, 8); return u; }

// ---------------- prologue: e -> half (swizzled) + esq + emax ----------------
__global__ void vq_prep_e(const float* __restrict__ e) {
    int c = blockIdx.x * blockDim.x + threadIdx.x;
    if (c == 0) g_flag_count = 0;
    if (c >= VQ_K) return;
    const float4* row = reinterpret_cast<const float4*>(e + (size_t)c * VQ_D);
    float s = 0.f;
#pragma unroll
    for (int g = 0; g < 8; g++) {  // granule g = halves 8g..8g+7
        float4 v0 = row[2 * g], v1 = row[2 * g + 1];
        s += v0.x * v0.x + v0.y * v0.y + v0.z * v0.z + v0.w * v0.w;
        s += v1.x * v1.x + v1.y * v1.y + v1.z * v1.z + v1.w * v1.w;
        __half2 h[4] = {__floats2half2_rn(v0.x, v0.y), __floats2half2_rn(v0.z, v0.w),
                        __floats2half2_rn(v1.x, v1.y), __floats2half2_rn(v1.z, v1.w)};
        uint4 pk;
        memcpy(&pk, h, 16);
        int gp = g ^ (c & 7);
        *reinterpret_cast<uint4*>(&g_eh[(size_t)c * VQ_D + gp * 8]) = pk;
    }
    g_esq[c] = s;
    atomicMax(&g_emax2_bits, __float_as_int(s));
}

// ---------------- prologue: x -> half (swizzled) ----------------
__global__ void vq_prep_x(const float* __restrict__ x) {
    int t = blockIdx.x * blockDim.x + threadIdx.x;  // B*8 threads
    int r = t >> 3, g = t & 7;
    const float4* p = reinterpret_cast<const float4*>(x + (size_t)r * VQ_D + g * 8);
    float4 v0 = p[0], v1 = p[1];
    __half2 h[4] = {__floats2half2_rn(v0.x, v0.y), __floats2half2_rn(v0.z, v0.w),
                    __floats2half2_rn(v1.x, v1.y), __floats2half2_rn(v1.z, v1.w)};
    uint4 pk;
    memcpy(&pk, h, 16);
    int gp = g ^ (r & 7);
    *reinterpret_cast<uint4*>(&g_xh[(size_t)r * VQ_D + gp * 8]) = pk;
}

// ---------------- main ----------------
__global__ void __launch_bounds__(THREADS) vq_main(const float* __restrict__ e,
                                                   float* __restrict__ out) {
    extern __shared__ __align__(16) unsigned char dsm[];
    const uint32_t sb = smem_u32(dsm);
    float* s_esq = reinterpret_cast<float*>(dsm + ESQ_OFF);
    float* s_xsq = reinterpret_cast<float*>(dsm + XSQ_OFF);
    __shared__ int s_widx[ROWS];

    const int tid = threadIdx.x;
    const int warp = tid >> 5, lane = tid & 31;
    const int row0 = blockIdx.x * ROWS;

    // Group0: x tile + esq + e chunk0.  Group1: e chunk1.
#pragma unroll
    for (int i = 0; i < 4; i++) {
        int line = tid + i * THREADS;  // 1024 x 16B
        CP_ASYNC16(sb + XS_OFF + line * 16,
                   reinterpret_cast<const char*>(g_xh) + (size_t)row0 * 128 + line * 16);
    }
    CP_ASYNC16(sb + ESQ_OFF + tid * 16, reinterpret_cast<const char*>(g_esq) + tid * 16);
#pragma unroll
    for (int i = 0; i < 4; i++) {
        int line = tid + i * THREADS;
        CP_ASYNC16(sb + ES_OFF + line * 16, reinterpret_cast<const char*>(g_eh) + line * 16);
    }
    CP_COMMIT();
#pragma unroll
    for (int i = 0; i < 4; i++) {
        int line = tid + i * THREADS;
        CP_ASYNC16(sb + ES_OFF + 16384 + line * 16,
                   reinterpret_cast<const char*>(g_eh) + 16384 + line * 16);
    }
    CP_COMMIT();

    uint32_t A[4][4];
    float xq0 = 0.f, xq1 = 0.f;
    // top-2 packed-key chains: rowA = warp*16 + lane/4, rowB = +8
    uint32_t k1a = 0xFFFFFFFFu, k2a = 0xFFFFFFFFu, k1b = 0xFFFFFFFFu, k2b = 0xFFFFFFFFu;

    for (int ch = 0; ch < NCHUNKS; ch++) {
        if (ch < NCHUNKS - 1) { CP_WAIT1(); } else { CP_WAIT0(); }
        __syncthreads();
        if (ch == 0) {
            // xsq from fp16 tile (any per-row constant works; swizzle is row-internal)
            if (tid < ROWS) {
                const __half2* p = reinterpret_cast<const __half2*>(dsm + XS_OFF + tid * 128);
                float s = 0.f;
#pragma unroll
                for (int i = 0; i < 32; i++) {
                    float2 f = __half22float2(p[i]);
                    s += f.x * f.x + f.y * f.y;
                }
                s_xsq[tid] = s;
            }
            __syncthreads();
            // A fragments: warp rows 16*warp..+15, 4 k-steps
#pragma unroll
            for (int ks = 0; ks < 4; ks++) {
                int r = warp * 16 + (lane & 15);
                int g = 2 * ks + (lane >> 4);
                uint32_t ad = sb + XS_OFF + (r * 64 + ((g ^ (r & 7)) * 8)) * 2;
                LDSM_X4(A[ks][0], A[ks][1], A[ks][2], A[ks][3], ad);
            }
            xq0 = s_xsq[warp * 16 + (lane >> 2)];
            xq1 = s_xsq[warp * 16 + (lane >> 2) + 8];
        }

        const uint32_t ebase = sb + ES_OFF + (ch & 1) * 16384;
        const int lc = lane & 7, lm = lane >> 3;
        uint32_t bA = ebase + (lc * 64 + ((lm ^ lc) * 8)) * 2;
        uint32_t bB = ebase + (lc * 64 + (((lm + 4) ^ lc) * 8)) * 2;
        const int gcl = 2 * (lane & 3);

#pragma unroll 4
        for (int nt = 0; nt < 16; nt++) {
            uint32_t b0, b1, b2, b3, b4, b5, b6, b7;
            LDSM_X4(b0, b1, b2, b3, bA + nt * 1024);
            LDSM_X4(b4, b5, b6, b7, bB + nt * 1024);
            float c0 = 0.f, c1 = 0.f, c2 = 0.f, c3 = 0.f;
            MMA16816(c0, c1, c2, c3, A[0][0], A[0][1], A[0][2], A[0][3], b0, b1);
            MMA16816(c0, c1, c2, c3, A[1][0], A[1][1], A[1][2], A[1][3], b2, b3);
            MMA16816(c0, c1, c2, c3, A[2][0], A[2][1], A[2][2], A[2][3], b4, b5);
            MMA16816(c0, c1, c2, c3, A[3][0], A[3][1], A[3][2], A[3][3], b6, b7);

            const int gc0 = ch * CHUNK + nt * 8 + gcl;
            float2 eq = *reinterpret_cast<const float2*>(s_esq + gc0);
            float s00 = fmaf(-2.f, c0, xq0 + eq.x);
            float s01 = fmaf(-2.f, c1, xq0 + eq.y);
            float s10 = fmaf(-2.f, c2, xq1 + eq.x);
            float s11 = fmaf(-2.f, c3, xq1 + eq.y);
            uint32_t u;
            u = (__float_as_uint(s00) & 0xFFFFFC00u) | (uint32_t)gc0;
            { uint32_t mx = max(k1a, u); k1a = min(k1a, u); k2a = min(k2a, mx); }
            u = (__float_as_uint(s01) & 0xFFFFFC00u) | (uint32_t)(gc0 + 1);
            { uint32_t mx = max(k1a, u); k1a = min(k1a, u); k2a = min(k2a, mx); }
            u = (__float_as_uint(s10) & 0xFFFFFC00u) | (uint32_t)gc0;
            { uint32_t mx = max(k1b, u); k1b = min(k1b, u); k2b = min(k2b, mx); }
            u = (__float_as_uint(s11) & 0xFFFFFC00u) | (uint32_t)(gc0 + 1);
            { uint32_t mx = max(k1b, u); k1b = min(k1b, u); k2b = min(k2b, mx); }
        }

        __syncthreads();
        if (ch + 2 < NCHUNKS) {
            uint32_t dst = sb + ES_OFF + (ch & 1) * 16384;
            const char* src = reinterpret_cast<const char*>(g_eh) + (size_t)(ch + 2) * 16384;
#pragma unroll
            for (int i = 0; i < 4; i++) {
                int line = tid + i * THREADS;
                CP_ASYNC16(dst + line * 16, src + line * 16);
            }
            CP_COMMIT();
        }
    }

    // merge top-2 chains across the 4 lanes of each row group
#pragma unroll
    for (int m = 1; m <= 2; m <<= 1) {
        uint32_t o1 = __shfl_xor_sync(0xFFFFFFFFu, k1a, m);
        uint32_t o2 = __shfl_xor_sync(0xFFFFFFFFu, k2a, m);
        uint32_t mx = max(k1a, o1);
        k1a = min(k1a, o1);
        k2a = min(min(k2a, o2), mx);
        o1 = __shfl_xor_sync(0xFFFFFFFFu, k1b, m);
        o2 = __shfl_xor_sync(0xFFFFFFFFu, k2b, m);
        mx = max(k1b, o1);
        k1b = min(k1b, o1);
        k2b = min(min(k2b, o2), mx);
    }

    if ((lane & 3) == 0) {
        const float emax = sqrtf(__int_as_float(g_emax2_bits));
#pragma unroll
        for (int h = 0; h < 2; h++) {
            uint32_t k1 = h ? k1b : k1a, k2 = h ? k2b : k2a;
            int r = warp * 16 + (lane >> 2) + h * 8;
            float m1 = __uint_as_float(k1 & 0xFFFFFC00u);
            float m2 = __uint_as_float(k2 & 0xFFFFFC00u);
            float margin = 0.0022f * sqrtf(s_xsq[r]) * emax + 0.06f;
            if (m2 - m1 < margin) {
                int slot = atomicAdd(&g_flag_count, 1);
                g_flag_rows[slot] = row0 + r;
            }
            s_widx[r] = (int)(k1 & 0x3FFu);
        }
    }
    __syncthreads();

    // gather winning embeddings (fp32 codebook), coalesced
#pragma unroll
    for (int i = 0; i < 8; i++) {
        int idx4 = tid + i * THREADS;
        int r = idx4 >> 4, q = idx4 & 15;
        int id = s_widx[r];
        *reinterpret_cast<float4*>(out + (size_t)(row0 + r) * VQ_D + q * 4) =
            *reinterpret_cast<const float4*>(e + (size_t)id * VQ_D + q * 4);
    }
}

// ---------------- fallback: exact fp32 rescan of flagged rows ----------------
__global__ void __launch_bounds__(256) vq_fallback(const float* __restrict__ x,
                                                   const float* __restrict__ e,
                                                   float* __restrict__ out) {
    __shared__ float se[64][68];
    __shared__ float sq[64];
    const int tid = threadIdx.x;
    const int wid = tid >> 5, lid = tid & 31;
    const int cnt = g_flag_count;

    for (int base = blockIdx.x * 8; base < cnt; base += gridDim.x * 8) {
        const int rown = base + wid;
        const int row = (rown < cnt) ? g_flag_rows[rown] : -1;
        uint64_t xrp[32];
        if (row >= 0) {
            const float2* xp = reinterpret_cast<const float2*>(x + (size_t)row * VQ_D);
#pragma unroll
            for (int i = 0; i < 32; i++) xrp[i] = f2u64(xp[i]);
        }
        float bs = FLT_MAX;
        int bi = 0x7fffffff;
        for (int cb = 0; cb < VQ_K; cb += 64) {
            __syncthreads();
#pragma unroll
            for (int i = 0; i < 4; i++) {
                int idx4 = tid + i * 256;
                int r = idx4 >> 4, q = idx4 & 15;
                *reinterpret_cast<float4*>(&se[r][q * 4]) =
                    *reinterpret_cast<const float4*>(e + (size_t)(cb + r) * VQ_D + q * 4);
            }
            if (tid < 64) sq[tid] = g_esq[cb + tid];
            __syncthreads();
            if (row >= 0) {
#pragma unroll
                for (int j = 0; j < 2; j++) {
                    int c = j * 32 + lid;
                    const ulonglong2* ev = reinterpret_cast<const ulonglong2*>(&se[c][0]);
                    uint64_t a0 = 0, a1 = 0, a2 = 0, a3 = 0;
#pragma unroll
                    for (int i = 0; i < 8; i++) {
                        ulonglong2 ea = ev[2 * i], eb = ev[2 * i + 1];
                        FMA_F32X2(a0, xrp[4 * i + 0], ea.x);
                        FMA_F32X2(a1, xrp[4 * i + 1], ea.y);
                        FMA_F32X2(a2, xrp[4 * i + 2], eb.x);
                        FMA_F32X2(a3, xrp[4 * i + 3], eb.y);
                    }
                    uint64_t s01, s23, st;
                    ADD_F32X2(s01, a0, a1);
                    ADD_F32X2(s23, a2, a3);
                    ADD_F32X2(st, s01, s23);
                    float2 sv = u64f2(st);
                    float s = fmaf(-2.f, sv.x + sv.y, sq[c]);
                    int code = cb + c;
                    if (s < bs) { bs = s; bi = code; }
                }
            }
        }
        if (row >= 0) {
#pragma unroll
            for (int o = 16; o > 0; o >>= 1) {
                float os = __shfl_down_sync(0xFFFFFFFF, bs, o);
                int oi = __shfl_down_sync(0xFFFFFFFF, bi, o);
                if (os < bs || (os == bs && oi < bi)) { bs = os; bi = oi; }
            }
            bi = __shfl_sync(0xFFFFFFFF, bi, 0);
            if (lid < 16)
                *reinterpret_cast<float4*>(out + (size_t)row * VQ_D + lid * 4) =
                    *reinterpret_cast<const float4*>(e + (size_t)bi * VQ_D + lid * 4);
        }
    }
}

extern "C" void kernel_launch(void* const* d_in, const int* in_sizes, int n_in,
                              void* d_out, int out_size) {
    const float* x = (const float*)d_in[0];           // (131072, 64)
    const float* embeddings = (const float*)d_in[1];  // (1024, 64)
    float* out = (float*)d_out;

    cudaFuncSetAttribute(vq_main, cudaFuncAttributeMaxDynamicSharedMemorySize, SMEM_TOTAL);

    vq_prep_e<<<VQ_K / 256, 256>>>(embeddings);
    vq_prep_x<<<(VQ_B * 8) / 256, 256>>>(x);
    vq_main<<<VQ_B / ROWS, THREADS, SMEM_TOTAL>>>(embeddings, out);
    vq_fallback<<<148, 256>>>(x, embeddings, out);
}

// round 5
// speedup vs baseline: 4.2876x; 1.4149x over previous
#include <cuda_runtime.h>
#include <cuda_fp16.h>
#include <cstdint>
#include <cstring>
#include <cfloat>

// VectorQuantizer: B=131072, D=64, K=1024, fp32.
// fp16 mma.sync GEMM + top-4 packed-key argmin + inline exact duel +
// margin-certified exact fallback (rare).

#define VQ_B 131072
#define VQ_K 1024
#define VQ_D 64
#define ROWS 128
#define THREADS 256
#define CHUNK 128
#define NCHUNKS 8

__device__ float g_esq[VQ_K];
__device__ int g_emax2_bits = 0;
__device__ int g_flag_count;
__device__ int g_flag_rows[VQ_B];
__device__ __half g_eh[(size_t)VQ_K * VQ_D];  // fp16 e, granule-swizzled

// Dynamic smem layout (bytes)
#define XS_OFF   0        // 128 rows * 128B fp16 = 16384
#define ES_OFF   16384    // 2 buffers * 16384
#define ESQ_OFF  49152    // 1024 floats
#define XSQ_OFF  53248    // 128 floats
#define SMEM_TOTAL 53760

// ---------------- PTX helpers ----------------
static __device__ __forceinline__ uint32_t smem_u32(const void* p) {
    uint32_t a;
    asm("{ .reg .u64 t; cvta.to.shared.u64 t, %1; cvt.u32.u64 %0, t; }" : "=r"(a) : "l"(p));
    return a;
}
#define CP_ASYNC16(dst, src) \
    asm volatile("cp.async.cg.shared.global [%0], [%1], 16;" :: "r"(dst), "l"(src) : "memory")
#define CP_COMMIT() asm volatile("cp.async.commit_group;" ::: "memory")
#define CP_WAIT1() asm volatile("cp.async.wait_group 1;" ::: "memory")
#define CP_WAIT0() asm volatile("cp.async.wait_group 0;" ::: "memory")
#define LDSM_X4(r0, r1, r2, r3, a) \
    asm volatile("ldmatrix.sync.aligned.m8n8.x4.shared.b16 {%0,%1,%2,%3}, [%4];" \
                 : "=r"(r0), "=r"(r1), "=r"(r2), "=r"(r3) : "r"(a))
#define MMA16816(c0, c1, c2, c3, a0, a1, a2, a3, b0, b1) \
    asm volatile("mma.sync.aligned.m16n8k16.row.col.f32.f16.f16.f32 " \
                 "{%0,%1,%2,%3}, {%4,%5,%6,%7}, {%8,%9}, {%0,%1,%2,%3};" \
                 : "+f"(c0), "+f"(c1), "+f"(c2), "+f"(c3) \
                 : "r"(a0), "r"(a1), "r"(a2), "r"(a3), "r"(b0), "r"(b1))

// sorted top-4 insert (keys ascending; k1<=k2<=k3<=k4)
#define INS4(k1, k2, k3, k4, u) do { \
    uint32_t _t1 = max(k1, u); k1 = min(k1, u); \
    uint32_t _t2 = max(k2, _t1); k2 = min(k2, _t1); \
    uint32_t _t3 = max(k3, _t2); k3 = min(k3, _t2); \
    k4 = min(k4, _t3); \
} while (0)

// f32x2 packed math (fallback kernel)
#define FMA_F32X2(acc, a, b) asm("fma.rn.f32x2 %0, %1, %2, %0;" : "+l"(acc) : "l"(a), "l"(b))
#define ADD_F32X2(d, a, b) asm("add.rn.f32x2 %0, %1, %2;" : "=l"(d) : "l"(a), "l"(b))
static __device__ __forceinline__ float2 u64f2(uint64_t u) { float2 v; memcpy(&v, &u, 8); return v; }
static __device__ __forceinline__ uint64_t f2u64(float2 v) { uint64_t u; memcpy(&u, &v, 8); return u; }

// ---------------- prologue: e -> half (swizzled) + esq + emax ----------------
__global__ void vq_prep_e(const float* __restrict__ e) {
    int c = blockIdx.x * blockDim.x + threadIdx.x;
    if (c == 0) g_flag_count = 0;
    if (c >= VQ_K) return;
    const float4* row = reinterpret_cast<const float4*>(e + (size_t)c * VQ_D);
    float s = 0.f;
#pragma unroll
    for (int g = 0; g < 8; g++) {
        float4 v0 = row[2 * g], v1 = row[2 * g + 1];
        s += v0.x * v0.x + v0.y * v0.y + v0.z * v0.z + v0.w * v0.w;
        s += v1.x * v1.x + v1.y * v1.y + v1.z * v1.z + v1.w * v1.w;
        __half2 h[4] = {__floats2half2_rn(v0.x, v0.y), __floats2half2_rn(v0.z, v0.w),
                        __floats2half2_rn(v1.x, v1.y), __floats2half2_rn(v1.z, v1.w)};
        uint4 pk;
        memcpy(&pk, h, 16);
        int gp = g ^ (c & 7);
        *reinterpret_cast<uint4*>(&g_eh[(size_t)c * VQ_D + gp * 8]) = pk;
    }
    g_esq[c] = s;
    atomicMax(&g_emax2_bits, __float_as_int(s));
}

static __device__ __forceinline__ float exact_score(const float4* xr, const float* e, int code) {
    const float4* er = reinterpret_cast<const float4*>(e + (size_t)code * VQ_D);
    float acc = 0.f;
#pragma unroll
    for (int i = 0; i < 16; i++) {
        float4 a = xr[i], b = er[i];
        acc = fmaf(a.x, b.x, acc); acc = fmaf(a.y, b.y, acc);
        acc = fmaf(a.z, b.z, acc); acc = fmaf(a.w, b.w, acc);
    }
    return fmaf(-2.f, acc, g_esq[code]);
}

// ---------------- main ----------------
__global__ void __launch_bounds__(THREADS) vq_main(const float* __restrict__ x,
                                                   const float* __restrict__ e,
                                                   float* __restrict__ out) {
    extern __shared__ __align__(16) unsigned char dsm[];
    const uint32_t sb = smem_u32(dsm);
    float* s_esq = reinterpret_cast<float*>(dsm + ESQ_OFF);
    float* s_xsq = reinterpret_cast<float*>(dsm + XSQ_OFF);
    __shared__ int s_widx[ROWS];

    const int tid = threadIdx.x;
    const int warp = tid >> 5, lane = tid & 31;
    const int row0 = blockIdx.x * ROWS;

    // e chunk 0 / esq / e chunk 1 via cp.async (2 groups)
    CP_ASYNC16(sb + ESQ_OFF + tid * 16, reinterpret_cast<const char*>(g_esq) + tid * 16);
#pragma unroll
    for (int i = 0; i < 4; i++) {
        int line = tid + i * THREADS;
        CP_ASYNC16(sb + ES_OFF + line * 16, reinterpret_cast<const char*>(g_eh) + line * 16);
    }
    CP_COMMIT();
#pragma unroll
    for (int i = 0; i < 4; i++) {
        int line = tid + i * THREADS;
        CP_ASYNC16(sb + ES_OFF + 16384 + line * 16,
                   reinterpret_cast<const char*>(g_eh) + 16384 + line * 16);
    }
    CP_COMMIT();

    // x tile: fp32 load -> fp16 convert -> swizzled STS (prep_x fused away)
#pragma unroll
    for (int i = 0; i < 8; i++) {
        int idx4 = tid + i * THREADS;  // 2048 float4
        int r = idx4 >> 4, q = idx4 & 15;
        float4 v = *reinterpret_cast<const float4*>(x + (size_t)(row0 + r) * VQ_D + q * 4);
        __half2 h0 = __floats2half2_rn(v.x, v.y), h1 = __floats2half2_rn(v.z, v.w);
        uint2 pk;
        memcpy(&pk.x, &h0, 4);
        memcpy(&pk.y, &h1, 4);
        int gp = (q >> 1) ^ (r & 7);
        *reinterpret_cast<uint2*>(dsm + XS_OFF + r * 128 + gp * 16 + (q & 1) * 8) = pk;
    }
    __syncthreads();
    if (tid < ROWS) {  // per-row squared norm (fp16 tile; row-constant, any const works)
        const __half2* p = reinterpret_cast<const __half2*>(dsm + XS_OFF + tid * 128);
        float s = 0.f;
#pragma unroll
        for (int i = 0; i < 32; i++) {
            float2 f = __half22float2(p[i]);
            s += f.x * f.x + f.y * f.y;
        }
        s_xsq[tid] = s;
    }
    __syncthreads();

    // A fragments: warp rows 16*warp..+15, 4 k-steps
    uint32_t A[4][4];
#pragma unroll
    for (int ks = 0; ks < 4; ks++) {
        int r = warp * 16 + (lane & 15);
        int g = 2 * ks + (lane >> 4);
        uint32_t ad = sb + XS_OFF + (r * 64 + ((g ^ (r & 7)) * 8)) * 2;
        LDSM_X4(A[ks][0], A[ks][1], A[ks][2], A[ks][3], ad);
    }
    const float xq0 = s_xsq[warp * 16 + (lane >> 2)];
    const float xq1 = s_xsq[warp * 16 + (lane >> 2) + 8];

    // top-4 packed-key chains per owned row (rowA = warp*16+lane/4, rowB = +8)
    uint32_t k1a = ~0u, k2a = ~0u, k3a = ~0u, k4a = ~0u;
    uint32_t k1b = ~0u, k2b = ~0u, k3b = ~0u, k4b = ~0u;

    for (int ch = 0; ch < NCHUNKS; ch++) {
        if (ch < NCHUNKS - 1) { CP_WAIT1(); } else { CP_WAIT0(); }
        __syncthreads();

        const uint32_t ebase = sb + ES_OFF + (ch & 1) * 16384;
        const int lc = lane & 7, lm = lane >> 3;
        uint32_t bA = ebase + (lc * 64 + ((lm ^ lc) * 8)) * 2;
        uint32_t bB = ebase + (lc * 64 + (((lm + 4) ^ lc) * 8)) * 2;
        const int gcl = 2 * (lane & 3);

#pragma unroll 4
        for (int nt = 0; nt < 16; nt++) {
            uint32_t b0, b1, b2, b3, b4, b5, b6, b7;
            LDSM_X4(b0, b1, b2, b3, bA + nt * 1024);
            LDSM_X4(b4, b5, b6, b7, bB + nt * 1024);
            float c0 = 0.f, c1 = 0.f, c2 = 0.f, c3 = 0.f;
            MMA16816(c0, c1, c2, c3, A[0][0], A[0][1], A[0][2], A[0][3], b0, b1);
            MMA16816(c0, c1, c2, c3, A[1][0], A[1][1], A[1][2], A[1][3], b2, b3);
            MMA16816(c0, c1, c2, c3, A[2][0], A[2][1], A[2][2], A[2][3], b4, b5);
            MMA16816(c0, c1, c2, c3, A[3][0], A[3][1], A[3][2], A[3][3], b6, b7);

            const int gc0 = ch * CHUNK + nt * 8 + gcl;
            float2 eq = *reinterpret_cast<const float2*>(s_esq + gc0);
            float p0 = xq0 + eq.x, p1 = xq0 + eq.y;
            float p2 = xq1 + eq.x, p3 = xq1 + eq.y;
            uint32_t u;
            u = (__float_as_uint(fmaf(-2.f, c0, p0)) & 0xFFFFFC00u) | (uint32_t)gc0;
            INS4(k1a, k2a, k3a, k4a, u);
            u = (__float_as_uint(fmaf(-2.f, c1, p1)) & 0xFFFFFC00u) | (uint32_t)(gc0 + 1);
            INS4(k1a, k2a, k3a, k4a, u);
            u = (__float_as_uint(fmaf(-2.f, c2, p2)) & 0xFFFFFC00u) | (uint32_t)gc0;
            INS4(k1b, k2b, k3b, k4b, u);
            u = (__float_as_uint(fmaf(-2.f, c3, p3)) & 0xFFFFFC00u) | (uint32_t)(gc0 + 1);
            INS4(k1b, k2b, k3b, k4b, u);
        }

        __syncthreads();
        if (ch + 2 < NCHUNKS) {
            uint32_t dst = sb + ES_OFF + (ch & 1) * 16384;
            const char* src = reinterpret_cast<const char*>(g_eh) + (size_t)(ch + 2) * 16384;
#pragma unroll
            for (int i = 0; i < 4; i++) {
                int line = tid + i * THREADS;
                CP_ASYNC16(dst + line * 16, src + line * 16);
            }
            CP_COMMIT();
        }
    }

    // merge top-4 lists across the 4 lanes of each row group
#pragma unroll
    for (int m = 1; m <= 2; m <<= 1) {
        uint32_t o1 = __shfl_xor_sync(~0u, k1a, m), o2 = __shfl_xor_sync(~0u, k2a, m);
        uint32_t o3 = __shfl_xor_sync(~0u, k3a, m), o4 = __shfl_xor_sync(~0u, k4a, m);
        INS4(k1a, k2a, k3a, k4a, o1);
        INS4(k1a, k2a, k3a, k4a, o2);
        INS4(k1a, k2a, k3a, k4a, o3);
        INS4(k1a, k2a, k3a, k4a, o4);
        o1 = __shfl_xor_sync(~0u, k1b, m); o2 = __shfl_xor_sync(~0u, k2b, m);
        o3 = __shfl_xor_sync(~0u, k3b, m); o4 = __shfl_xor_sync(~0u, k4b, m);
        INS4(k1b, k2b, k3b, k4b, o1);
        INS4(k1b, k2b, k3b, k4b, o2);
        INS4(k1b, k2b, k3b, k4b, o3);
        INS4(k1b, k2b, k3b, k4b, o4);
    }

    if ((lane & 3) == 0) {
        const float emax = sqrtf(__int_as_float(g_emax2_bits));
#pragma unroll
        for (int h = 0; h < 2; h++) {
            uint32_t k1 = h ? k1b : k1a, k2 = h ? k2b : k2a;
            uint32_t k3 = h ? k3b : k3a, k4 = h ? k4b : k4a;
            int r = warp * 16 + (lane >> 2) + h * 8;
            float m1 = __uint_as_float(k1 & 0xFFFFFC00u);
            float m2 = __uint_as_float(k2 & 0xFFFFFC00u);
            float m4 = __uint_as_float(k4 & 0xFFFFFC00u);
            float margin = 0.0022f * sqrtf(s_xsq[r]) * emax + 0.06f;
            int winner = (int)(k1 & 0x3FFu);
            if (m2 - m1 < margin) {
                if (m4 - m1 >= margin) {
                    // true winner provably in {i1,i2,i3}: exact fp32 duel
                    const float4* xr =
                        reinterpret_cast<const float4*>(x + (size_t)(row0 + r) * VQ_D);
                    int i1 = winner, i2 = (int)(k2 & 0x3FFu), i3 = (int)(k3 & 0x3FFu);
                    float s1 = exact_score(xr, e, i1);
                    float s2 = exact_score(xr, e, i2);
                    float s3 = exact_score(xr, e, i3);
                    if (s2 < s1 || (s2 == s1 && i2 < i1)) { s1 = s2; winner = i2; }
                    if (s3 < s1 || (s3 == s1 && i3 < winner)) { winner = i3; }
                } else {
                    int slot = atomicAdd(&g_flag_count, 1);
                    g_flag_rows[slot] = row0 + r;
                }
            }
            s_widx[r] = winner;
        }
    }
    __syncthreads();

    // gather winning embeddings (fp32 codebook), coalesced
#pragma unroll
    for (int i = 0; i < 8; i++) {
        int idx4 = tid + i * THREADS;
        int r = idx4 >> 4, q = idx4 & 15;
        int id = s_widx[r];
        *reinterpret_cast<float4*>(out + (size_t)(row0 + r) * VQ_D + q * 4) =
            *reinterpret_cast<const float4*>(e + (size_t)id * VQ_D + q * 4);
    }
}

// ---------------- fallback: exact fp32 rescan of flagged rows (rare) ----------------
__global__ void __launch_bounds__(256) vq_fallback(const float* __restrict__ x,
                                                   const float* __restrict__ e,
                                                   float* __restrict__ out) {
    __shared__ float se[64][68];
    __shared__ float sq[64];
    const int tid = threadIdx.x;
    const int wid = tid >> 5, lid = tid & 31;
    const int cnt = g_flag_count;

    for (int base = blockIdx.x * 8; base < cnt; base += gridDim.x * 8) {
        const int rown = base + wid;
        const int row = (rown < cnt) ? g_flag_rows[rown] : -1;
        uint64_t xrp[32];
        if (row >= 0) {
            const float2* xp = reinterpret_cast<const float2*>(x + (size_t)row * VQ_D);
#pragma unroll
            for (int i = 0; i < 32; i++) xrp[i] = f2u64(xp[i]);
        }
        float bs = FLT_MAX;
        int bi = 0x7fffffff;
        for (int cb = 0; cb < VQ_K; cb += 64) {
            __syncthreads();
#pragma unroll
            for (int i = 0; i < 4; i++) {
                int idx4 = tid + i * 256;
                int r = idx4 >> 4, q = idx4 & 15;
                *reinterpret_cast<float4*>(&se[r][q * 4]) =
                    *reinterpret_cast<const float4*>(e + (size_t)(cb + r) * VQ_D + q * 4);
            }
            if (tid < 64) sq[tid] = g_esq[cb + tid];
            __syncthreads();
            if (row >= 0) {
#pragma unroll
                for (int j = 0; j < 2; j++) {
                    int c = j * 32 + lid;
                    const ulonglong2* ev = reinterpret_cast<const ulonglong2*>(&se[c][0]);
                    uint64_t a0 = 0, a1 = 0, a2 = 0, a3 = 0;
#pragma unroll
                    for (int i = 0; i < 8; i++) {
                        ulonglong2 ea = ev[2 * i], eb = ev[2 * i + 1];
                        FMA_F32X2(a0, xrp[4 * i + 0], ea.x);
                        FMA_F32X2(a1, xrp[4 * i + 1], ea.y);
                        FMA_F32X2(a2, xrp[4 * i + 2], eb.x);
                        FMA_F32X2(a3, xrp[4 * i + 3], eb.y);
                    }
                    uint64_t s01, s23, st;
                    ADD_F32X2(s01, a0, a1);
                    ADD_F32X2(s23, a2, a3);
                    ADD_F32X2(st, s01, s23);
                    float2 sv = u64f2(st);
                    float s = fmaf(-2.f, sv.x + sv.y, sq[c]);
                    int code = cb + c;
                    if (s < bs) { bs = s; bi = code; }
                }
            }
        }
        if (row >= 0) {
#pragma unroll
            for (int o = 16; o > 0; o >>= 1) {
                float os = __shfl_down_sync(0xFFFFFFFF, bs, o);
                int oi = __shfl_down_sync(0xFFFFFFFF, bi, o);
                if (os < bs || (os == bs && oi < bi)) { bs = os; bi = oi; }
            }
            bi = __shfl_sync(0xFFFFFFFF, bi, 0);
            if (lid < 16)
                *reinterpret_cast<float4*>(out + (size_t)row * VQ_D + lid * 4) =
                    *reinterpret_cast<const float4*>(e + (size_t)bi * VQ_D + lid * 4);
        }
    }
}

extern "C" void kernel_launch(void* const* d_in, const int* in_sizes, int n_in,
                              void* d_out, int out_size) {
    const float* x = (const float*)d_in[0];           // (131072, 64)
    const float* embeddings = (const float*)d_in[1];  // (1024, 64)
    float* out = (float*)d_out;

    cudaFuncSetAttribute(vq_main, cudaFuncAttributeMaxDynamicSharedMemorySize, SMEM_TOTAL);

    vq_prep_e<<<VQ_K / 256, 256>>>(embeddings);
    vq_main<<<VQ_B / ROWS, THREADS, SMEM_TOTAL>>>(x, embeddings, out);
    vq_fallback<<<1024, 256>>>(x, embeddings, out);
}

// round 6
// speedup vs baseline: 4.3478x; 1.0140x over previous
#include <cuda_runtime.h>
#include <cuda_fp16.h>
#include <cstdint>
#include <cstring>
#include <cfloat>

// VectorQuantizer: B=131072, D=64, K=1024, fp32.
// Persistent-CTA fp16 mma.sync GEMM with the whole codebook resident in smem,
// top-4 packed-key argmin + inline exact duel + rare exact fallback.

#define VQ_B 131072
#define VQ_K 1024
#define VQ_D 64
#define ROWS 128
#define THREADS 256
#define NTILES (VQ_B / ROWS)   // 1024
#define GRID_MAIN 148
#define NCHUNKS 8

__device__ float g_esq[VQ_K];
__device__ int g_emax2_bits = 0;
__device__ int g_flag_count;
__device__ int g_flag_rows[VQ_B];
__device__ __half g_eh[(size_t)VQ_K * VQ_D];   // fp16 e, granule-swizzled
__device__ __half g_xh[(size_t)VQ_B * VQ_D];   // fp16 x, granule-swizzled

// Dynamic smem layout (bytes)
#define ES_OFF   0         // full codebook: 1024 rows * 128B = 131072
#define XS_OFF   131072    // 2 x-tile buffers * 16384
#define ESQ_OFF  163840    // 1024 floats
#define SMEM_TOTAL 167936

// ---------------- PTX helpers ----------------
static __device__ __forceinline__ uint32_t smem_u32(const void* p) {
    uint32_t a;
    asm("{ .reg .u64 t; cvta.to.shared.u64 t, %1; cvt.u32.u64 %0, t; }" : "=r"(a) : "l"(p));
    return a;
}
#define CP_ASYNC16(dst, src) \
    asm volatile("cp.async.cg.shared.global [%0], [%1], 16;" :: "r"(dst), "l"(src) : "memory")
#define CP_COMMIT() asm volatile("cp.async.commit_group;" ::: "memory")
#define CP_WAIT0() asm volatile("cp.async.wait_group 0;" ::: "memory")
#define LDSM_X4(r0, r1, r2, r3, a) \
    asm volatile("ldmatrix.sync.aligned.m8n8.x4.shared.b16 {%0,%1,%2,%3}, [%4];" \
                 : "=r"(r0), "=r"(r1), "=r"(r2), "=r"(r3) : "r"(a))
#define MMA16816(c0, c1, c2, c3, a0, a1, a2, a3, b0, b1) \
    asm volatile("mma.sync.aligned.m16n8k16.row.col.f32.f16.f16.f32 " \
                 "{%0,%1,%2,%3}, {%4,%5,%6,%7}, {%8,%9}, {%0,%1,%2,%3};" \
                 : "+f"(c0), "+f"(c1), "+f"(c2), "+f"(c3) \
                 : "r"(a0), "r"(a1), "r"(a2), "r"(a3), "r"(b0), "r"(b1))

// sorted top-4 insert (keys ascending; k1<=k2<=k3<=k4)
#define INS4(k1, k2, k3, k4, u) do { \
    uint32_t _t1 = max(k1, u); k1 = min(k1, u); \
    uint32_t _t2 = max(k2, _t1); k2 = min(k2, _t1); \
    uint32_t _t3 = max(k3, _t2); k3 = min(k3, _t2); \
    k4 = min(k4, _t3); \
} while (0)

// f32x2 packed math (fallback kernel)
#define FMA_F32X2(acc, a, b) asm("fma.rn.f32x2 %0, %1, %2, %0;" : "+l"(acc) : "l"(a), "l"(b))
#define ADD_F32X2(d, a, b) asm("add.rn.f32x2 %0, %1, %2;" : "=l"(d) : "l"(a), "l"(b))
static __device__ __forceinline__ float2 u64f2(uint64_t u) { float2 v; memcpy(&v, &u, 8); return v; }
static __device__ __forceinline__ uint64_t f2u64(float2 v) { uint64_t u; memcpy(&u, &v, 8); return u; }

// ---------------- prologue: x AND e -> fp16 (granule-swizzled) ----------------
__global__ void vq_prep(const float* __restrict__ x, const float* __restrict__ e) {
    int t = blockIdx.x * blockDim.x + threadIdx.x;  // VQ_B*8 threads
    if (t == 0) g_flag_count = 0;

    {   // x: thread handles one 8-dim granule of one row
        int r = t >> 3, g = t & 7;
        const float4* p = reinterpret_cast<const float4*>(x + (size_t)r * VQ_D + g * 8);
        float4 v0 = p[0], v1 = p[1];
        __half2 h[4] = {__floats2half2_rn(v0.x, v0.y), __floats2half2_rn(v0.z, v0.w),
                        __floats2half2_rn(v1.x, v1.y), __floats2half2_rn(v1.z, v1.w)};
        uint4 pk;
        memcpy(&pk, h, 16);
        int gp = g ^ (r & 7);
        *reinterpret_cast<uint4*>(&g_xh[(size_t)r * VQ_D + gp * 8]) = pk;
    }

    if (t < VQ_K) {  // e: thread handles a whole codebook row + esq
        int c = t;
        const float4* row = reinterpret_cast<const float4*>(e + (size_t)c * VQ_D);
        float s = 0.f;
#pragma unroll
        for (int g = 0; g < 8; g++) {
            float4 v0 = row[2 * g], v1 = row[2 * g + 1];
            s += v0.x * v0.x + v0.y * v0.y + v0.z * v0.z + v0.w * v0.w;
            s += v1.x * v1.x + v1.y * v1.y + v1.z * v1.z + v1.w * v1.w;
            __half2 h[4] = {__floats2half2_rn(v0.x, v0.y), __floats2half2_rn(v0.z, v0.w),
                            __floats2half2_rn(v1.x, v1.y), __floats2half2_rn(v1.z, v1.w)};
            uint4 pk;
            memcpy(&pk, h, 16);
            int gp = g ^ (c & 7);
            *reinterpret_cast<uint4*>(&g_eh[(size_t)c * VQ_D + gp * 8]) = pk;
        }
        g_esq[c] = s;
        atomicMax(&g_emax2_bits, __float_as_int(s));
    }
}

// exact fp32 score with 4 split accumulators (short dependency chains)
static __device__ __forceinline__ float exact_score(const float4* xr, const float* e, int code,
                                                    float esq) {
    const float4* er = reinterpret_cast<const float4*>(e + (size_t)code * VQ_D);
    float a0 = 0.f, a1 = 0.f, a2 = 0.f, a3 = 0.f;
#pragma unroll
    for (int i = 0; i < 16; i += 4) {
        float4 xa = xr[i], ba = er[i];
        float4 xb = xr[i + 1], bb = er[i + 1];
        float4 xc = xr[i + 2], bc = er[i + 2];
        float4 xd = xr[i + 3], bd = er[i + 3];
        a0 = fmaf(xa.x, ba.x, a0); a0 = fmaf(xa.y, ba.y, a0);
        a0 = fmaf(xa.z, ba.z, a0); a0 = fmaf(xa.w, ba.w, a0);
        a1 = fmaf(xb.x, bb.x, a1); a1 = fmaf(xb.y, bb.y, a1);
        a1 = fmaf(xb.z, bb.z, a1); a1 = fmaf(xb.w, bb.w, a1);
        a2 = fmaf(xc.x, bc.x, a2); a2 = fmaf(xc.y, bc.y, a2);
        a2 = fmaf(xc.z, bc.z, a2); a2 = fmaf(xc.w, bc.w, a2);
        a3 = fmaf(xd.x, bd.x, a3); a3 = fmaf(xd.y, bd.y, a3);
        a3 = fmaf(xd.z, bd.z, a3); a3 = fmaf(xd.w, bd.w, a3);
    }
    return fmaf(-2.f, (a0 + a1) + (a2 + a3), esq);
}

// ---------------- main: persistent CTAs, codebook resident in smem ----------------
__global__ void __launch_bounds__(THREADS, 1) vq_main(const float* __restrict__ x,
                                                      const float* __restrict__ e,
                                                      float* __restrict__ out) {
    extern __shared__ __align__(16) unsigned char dsm[];
    const uint32_t sb = smem_u32(dsm);
    float* s_esq = reinterpret_cast<float*>(dsm + ESQ_OFF);
    __shared__ int s_widx[ROWS];

    const int tid = threadIdx.x;
    const int warp = tid >> 5, lane = tid & 31;

    // ---- one-time loads: full codebook (128KB) + esq + first x tile ----
#pragma unroll
    for (int i = 0; i < 32; i++) {
        int line = tid + i * THREADS;  // 8192 x 16B
        CP_ASYNC16(sb + ES_OFF + line * 16, reinterpret_cast<const char*>(g_eh) + line * 16);
    }
    CP_ASYNC16(sb + ESQ_OFF + tid * 16, reinterpret_cast<const char*>(g_esq) + tid * 16);
    {
        size_t src0 = (size_t)blockIdx.x * 16384;
#pragma unroll
        for (int i = 0; i < 4; i++) {
            int line = tid + i * THREADS;
            CP_ASYNC16(sb + XS_OFF + line * 16, reinterpret_cast<const char*>(g_xh) + src0 + line * 16);
        }
    }
    CP_COMMIT();
    CP_WAIT0();
    __syncthreads();

    const float emax = sqrtf(__int_as_float(g_emax2_bits));
    const int lc = lane & 7, lm = lane >> 3;
    const uint32_t bA0 = sb + ES_OFF + (lc * 64 + ((lm ^ lc) * 8)) * 2;
    const uint32_t bB0 = sb + ES_OFF + (lc * 64 + (((lm + 4) ^ lc) * 8)) * 2;
    const int gcl = 2 * (lane & 3);

    int buf = 0;
    for (int tile = blockIdx.x; tile < NTILES; tile += GRID_MAIN, buf ^= 1) {
        const int row0 = tile * ROWS;
        const uint32_t xs = sb + XS_OFF + buf * 16384;

        // A fragments: warp rows 16*warp..+15, 4 k-steps
        uint32_t A[4][4];
#pragma unroll
        for (int ks = 0; ks < 4; ks++) {
            int r = warp * 16 + (lane & 15);
            int g = 2 * ks + (lane >> 4);
            uint32_t ad = xs + (r * 64 + ((g ^ (r & 7)) * 8)) * 2;
            LDSM_X4(A[ks][0], A[ks][1], A[ks][2], A[ks][3], ad);
        }

        // prefetch next x tile into the other buffer
        if (tile + GRID_MAIN < NTILES) {
            size_t srcn = (size_t)(tile + GRID_MAIN) * 16384;
            uint32_t dst = sb + XS_OFF + (buf ^ 1) * 16384;
#pragma unroll
            for (int i = 0; i < 4; i++) {
                int line = tid + i * THREADS;
                CP_ASYNC16(dst + line * 16, reinterpret_cast<const char*>(g_xh) + srcn + line * 16);
            }
            CP_COMMIT();
        }

        // per-row squared norms from A fragments (rows rA = warp*16+lane/4, rB = +8)
        float xq0, xq1;
        {
            float t0 = 0.f, t1 = 0.f;
#pragma unroll
            for (int ks = 0; ks < 4; ks++) {
                float2 f;
                f = __half22float2(*reinterpret_cast<__half2*>(&A[ks][0]));
                t0 = fmaf(f.x, f.x, t0); t0 = fmaf(f.y, f.y, t0);
                f = __half22float2(*reinterpret_cast<__half2*>(&A[ks][2]));
                t0 = fmaf(f.x, f.x, t0); t0 = fmaf(f.y, f.y, t0);
                f = __half22float2(*reinterpret_cast<__half2*>(&A[ks][1]));
                t1 = fmaf(f.x, f.x, t1); t1 = fmaf(f.y, f.y, t1);
                f = __half22float2(*reinterpret_cast<__half2*>(&A[ks][3]));
                t1 = fmaf(f.x, f.x, t1); t1 = fmaf(f.y, f.y, t1);
            }
            t0 += __shfl_xor_sync(~0u, t0, 1); t0 += __shfl_xor_sync(~0u, t0, 2);
            t1 += __shfl_xor_sync(~0u, t1, 1); t1 += __shfl_xor_sync(~0u, t1, 2);
            xq0 = t0; xq1 = t1;
        }

        // top-4 packed-key chains per owned row
        uint32_t k1a = ~0u, k2a = ~0u, k3a = ~0u, k4a = ~0u;
        uint32_t k1b = ~0u, k2b = ~0u, k3b = ~0u, k4b = ~0u;

        for (int ch = 0; ch < NCHUNKS; ch++) {
            const uint32_t bA = bA0 + ch * 16384, bB = bB0 + ch * 16384;
#pragma unroll 4
            for (int nt = 0; nt < 16; nt++) {
                uint32_t b0, b1, b2, b3, b4, b5, b6, b7;
                LDSM_X4(b0, b1, b2, b3, bA + nt * 1024);
                LDSM_X4(b4, b5, b6, b7, bB + nt * 1024);
                float c0 = 0.f, c1 = 0.f, c2 = 0.f, c3 = 0.f;
                MMA16816(c0, c1, c2, c3, A[0][0], A[0][1], A[0][2], A[0][3], b0, b1);
                MMA16816(c0, c1, c2, c3, A[1][0], A[1][1], A[1][2], A[1][3], b2, b3);
                MMA16816(c0, c1, c2, c3, A[2][0], A[2][1], A[2][2], A[2][3], b4, b5);
                MMA16816(c0, c1, c2, c3, A[3][0], A[3][1], A[3][2], A[3][3], b6, b7);

                const int gc0 = ch * 128 + nt * 8 + gcl;
                float2 eq = *reinterpret_cast<const float2*>(s_esq + gc0);
                float p0 = xq0 + eq.x, p1 = xq0 + eq.y;
                float p2 = xq1 + eq.x, p3 = xq1 + eq.y;
                uint32_t u;
                u = (__float_as_uint(fmaf(-2.f, c0, p0)) & 0xFFFFFC00u) | (uint32_t)gc0;
                INS4(k1a, k2a, k3a, k4a, u);
                u = (__float_as_uint(fmaf(-2.f, c1, p1)) & 0xFFFFFC00u) | (uint32_t)(gc0 + 1);
                INS4(k1a, k2a, k3a, k4a, u);
                u = (__float_as_uint(fmaf(-2.f, c2, p2)) & 0xFFFFFC00u) | (uint32_t)gc0;
                INS4(k1b, k2b, k3b, k4b, u);
                u = (__float_as_uint(fmaf(-2.f, c3, p3)) & 0xFFFFFC00u) | (uint32_t)(gc0 + 1);
                INS4(k1b, k2b, k3b, k4b, u);
            }
        }

        // merge top-4 lists across the 4 lanes of each row quad
#pragma unroll
        for (int m = 1; m <= 2; m <<= 1) {
            uint32_t o1 = __shfl_xor_sync(~0u, k1a, m), o2 = __shfl_xor_sync(~0u, k2a, m);
            uint32_t o3 = __shfl_xor_sync(~0u, k3a, m), o4 = __shfl_xor_sync(~0u, k4a, m);
            INS4(k1a, k2a, k3a, k4a, o1);
            INS4(k1a, k2a, k3a, k4a, o2);
            INS4(k1a, k2a, k3a, k4a, o3);
            INS4(k1a, k2a, k3a, k4a, o4);
            o1 = __shfl_xor_sync(~0u, k1b, m); o2 = __shfl_xor_sync(~0u, k2b, m);
            o3 = __shfl_xor_sync(~0u, k3b, m); o4 = __shfl_xor_sync(~0u, k4b, m);
            INS4(k1b, k2b, k3b, k4b, o1);
            INS4(k1b, k2b, k3b, k4b, o2);
            INS4(k1b, k2b, k3b, k4b, o3);
            INS4(k1b, k2b, k3b, k4b, o4);
        }

        if ((lane & 3) == 0) {
#pragma unroll
            for (int h = 0; h < 2; h++) {
                uint32_t k1 = h ? k1b : k1a, k2 = h ? k2b : k2a;
                uint32_t k3 = h ? k3b : k3a, k4 = h ? k4b : k4a;
                int r = warp * 16 + (lane >> 2) + h * 8;
                float xq = h ? xq1 : xq0;
                float m1 = __uint_as_float(k1 & 0xFFFFFC00u);
                float m2 = __uint_as_float(k2 & 0xFFFFFC00u);
                float m4 = __uint_as_float(k4 & 0xFFFFFC00u);
                float margin = 0.0022f * sqrtf(xq) * emax + 0.06f;
                int winner = (int)(k1 & 0x3FFu);
                if (m2 - m1 < margin) {
                    if (m4 - m1 >= margin) {
                        const float4* xr =
                            reinterpret_cast<const float4*>(x + (size_t)(row0 + r) * VQ_D);
                        int i1 = winner, i2 = (int)(k2 & 0x3FFu), i3 = (int)(k3 & 0x3FFu);
                        float s1 = exact_score(xr, e, i1, s_esq[i1]);
                        float s2 = exact_score(xr, e, i2, s_esq[i2]);
                        float s3 = exact_score(xr, e, i3, s_esq[i3]);
                        if (s2 < s1 || (s2 == s1 && i2 < i1)) { s1 = s2; winner = i2; }
                        if (s3 < s1 || (s3 == s1 && i3 < winner)) { winner = i3; }
                    } else {
                        int slot = atomicAdd(&g_flag_count, 1);
                        g_flag_rows[slot] = row0 + r;
                    }
                }
                s_widx[r] = winner;
            }
        }
        __syncthreads();

        // gather winning embeddings (fp32 codebook, L2-resident), coalesced writes
#pragma unroll
        for (int i = 0; i < 8; i++) {
            int idx4 = tid + i * THREADS;
            int r = idx4 >> 4, q = idx4 & 15;
            int id = s_widx[r];
            *reinterpret_cast<float4*>(out + (size_t)(row0 + r) * VQ_D + q * 4) =
                *reinterpret_cast<const float4*>(e + (size_t)id * VQ_D + q * 4);
        }

        CP_WAIT0();
        __syncthreads();
    }
}

// ---------------- fallback: exact fp32 rescan of flagged rows (rare) ----------------
__global__ void __launch_bounds__(256) vq_fallback(const float* __restrict__ x,
                                                   const float* __restrict__ e,
                                                   float* __restrict__ out) {
    __shared__ float se[64][68];
    __shared__ float sq[64];
    const int tid = threadIdx.x;
    const int wid = tid >> 5, lid = tid & 31;
    const int cnt = g_flag_count;

    for (int base = blockIdx.x * 8; base < cnt; base += gridDim.x * 8) {
        const int rown = base + wid;
        const int row = (rown < cnt) ? g_flag_rows[rown] : -1;
        uint64_t xrp[32];
        if (row >= 0) {
            const float2* xp = reinterpret_cast<const float2*>(x + (size_t)row * VQ_D);
#pragma unroll
            for (int i = 0; i < 32; i++) xrp[i] = f2u64(xp[i]);
        }
        float bs = FLT_MAX;
        int bi = 0x7fffffff;
        for (int cb = 0; cb < VQ_K; cb += 64) {
            __syncthreads();
#pragma unroll
            for (int i = 0; i < 4; i++) {
                int idx4 = tid + i * 256;
                int r = idx4 >> 4, q = idx4 & 15;
                *reinterpret_cast<float4*>(&se[r][q * 4]) =
                    *reinterpret_cast<const float4*>(e + (size_t)(cb + r) * VQ_D + q * 4);
            }
            if (tid < 64) sq[tid] = g_esq[cb + tid];
            __syncthreads();
            if (row >= 0) {
#pragma unroll
                for (int j = 0; j < 2; j++) {
                    int c = j * 32 + lid;
                    const ulonglong2* ev = reinterpret_cast<const ulonglong2*>(&se[c][0]);
                    uint64_t a0 = 0, a1 = 0, a2 = 0, a3 = 0;
#pragma unroll
                    for (int i = 0; i < 8; i++) {
                        ulonglong2 ea = ev[2 * i], eb = ev[2 * i + 1];
                        FMA_F32X2(a0, xrp[4 * i + 0], ea.x);
                        FMA_F32X2(a1, xrp[4 * i + 1], ea.y);
                        FMA_F32X2(a2, xrp[4 * i + 2], eb.x);
                        FMA_F32X2(a3, xrp[4 * i + 3], eb.y);
                    }
                    uint64_t s01, s23, st;
                    ADD_F32X2(s01, a0, a1);
                    ADD_F32X2(s23, a2, a3);
                    ADD_F32X2(st, s01, s23);
                    float2 sv = u64f2(st);
                    float s = fmaf(-2.f, sv.x + sv.y, sq[c]);
                    int code = cb + c;
                    if (s < bs) { bs = s; bi = code; }
                }
            }
        }
        if (row >= 0) {
#pragma unroll
            for (int o = 16; o > 0; o >>= 1) {
                float os = __shfl_down_sync(0xFFFFFFFF, bs, o);
                int oi = __shfl_down_sync(0xFFFFFFFF, bi, o);
                if (os < bs || (os == bs && oi < bi)) { bs = os; bi = oi; }
            }
            bi = __shfl_sync(0xFFFFFFFF, bi, 0);
            if (lid < 16)
                *reinterpret_cast<float4*>(out + (size_t)row * VQ_D + lid * 4) =
                    *reinterpret_cast<const float4*>(e + (size_t)bi * VQ_D + lid * 4);
        }
    }
}

extern "C" void kernel_launch(void* const* d_in, const int* in_sizes, int n_in,
                              void* d_out, int out_size) {
    const float* x = (const float*)d_in[0];           // (131072, 64)
    const float* embeddings = (const float*)d_in[1];  // (1024, 64)
    float* out = (float*)d_out;

    cudaFuncSetAttribute(vq_main, cudaFuncAttributeMaxDynamicSharedMemorySize, SMEM_TOTAL);

    vq_prep<<<(VQ_B * 8) / 256, 256>>>(x, embeddings);
    vq_main<<<GRID_MAIN, THREADS, SMEM_TOTAL>>>(x, embeddings, out);
    vq_fallback<<<1024, 256>>>(x, embeddings, out);
}